// round 2
// baseline (speedup 1.0000x reference)
#include <cuda_runtime.h>
#include <math_constants.h>
#include <cstddef>

#define B_  16
#define T_  750
#define D_  2048
#define C_  20
constexpr int M_TOTAL = B_ * T_;     // 12000
constexpr int K_DIM   = 3 * D_;      // 6144
constexpr int K_EASY  = T_ / 5;      // 150
constexpr int K_HARD  = T_ / 20;     // 37

// ---- output offsets (flattened reference tuple, all f32) ----
constexpr size_t OFF_VS  = 0;
constexpr size_t OFF_EA  = OFF_VS + (size_t)B_ * C_;
constexpr size_t OFF_EB  = OFF_EA + (size_t)B_ * K_EASY * D_;
constexpr size_t OFF_HA  = OFF_EB + (size_t)B_ * K_EASY * D_;
constexpr size_t OFF_HB  = OFF_HA + (size_t)B_ * K_HARD * D_;
constexpr size_t OFF_ACT = OFF_HB + (size_t)B_ * K_HARD * D_;
constexpr size_t OFF_CAS = OFF_ACT + (size_t)B_ * T_;

// ---- scratch ----
__device__ float g_xp[(size_t)B_ * 752 * D_];
__device__ float g_w1r[(size_t)K_DIM * D_];
__device__ float g_w2t[D_ * C_];
__device__ float g_h[(size_t)M_TOTAL * D_];
__device__ int   g_idx[2 * (B_ * K_EASY) + 2 * (B_ * K_HARD)];
__device__ float g_means[B_ * C_];

// ============================================================
__global__ void pad_x_k(const float* __restrict__ x) {
    int idx = blockIdx.x * blockDim.x + threadIdx.x;
    const int per_b = 752 * (D_ / 4);
    if (idx >= B_ * per_b) return;
    int b  = idx / per_b;
    int r  = idx - b * per_b;
    int t  = r >> 9;
    int d4 = r & 511;
    float4 v = make_float4(0.f, 0.f, 0.f, 0.f);
    if (t >= 1 && t <= T_) {
        v = ((const float4*)x)[((size_t)(b * T_ + (t - 1)) << 9) + d4];
    }
    ((float4*)g_xp)[idx] = v;
}

__global__ void repack_w1_k(const float* __restrict__ w1) {
    __shared__ float sh[32][33];
    int ic0 = blockIdx.x * 32;
    int d0  = blockIdx.y * 32;
    int tx = threadIdx.x, ty = threadIdx.y;
    sh[ty][tx] = w1[(size_t)(d0 + ty) * K_DIM + ic0 + tx];
    __syncthreads();
    int ic = ic0 + ty;
    int io = ic / 3, ko = ic - io * 3;
    g_w1r[((size_t)(ko * D_ + io)) * D_ + d0 + tx] = sh[tx][ty];
}

__global__ void repack_w2_k(const float* __restrict__ w2) {
    int o = blockIdx.x * blockDim.x + threadIdx.x;
    if (o >= D_ * C_) return;
    int d = o / C_, c = o - d * C_;
    g_w2t[o] = w2[(size_t)c * D_ + d];
}

// ============================================================
// conv1 as SGEMM with Kahan-compensated accumulation.
// M=12000(+pad), N=2048, K=6144. 128x128x8 tiles, 512 threads, 8x4/thread.
// Partial p accumulates 4 K-tiles (32 terms) in fp32, then Kahan-folds
// into (acc, comp). Total h error ~3e-7 vs exact.
// ============================================================
__global__ __launch_bounds__(512, 1) void conv1_gemm(const float* __restrict__ b1) {
    __shared__ float As[2][8][132];
    __shared__ float Bs[2][8][128];

    const int tid = threadIdx.x;
    const int bn = blockIdx.x;
    const int bm = blockIdx.y;

    // global-load role: tid<256 loads A (one float4/stage), else B
    const bool isA = tid < 256;
    const int aRow = (tid & 255) >> 1;
    const int aCol = (tid & 1) << 2;
    int m = bm * 128 + aRow;
    int mc = (m < M_TOTAL) ? m : 0;
    const int bb = mc / T_, tt = mc - bb * T_;
    const float* aPtr = g_xp + (((size_t)(bb * 752 + tt)) << 11) + aCol;

    const int t2 = tid - 256;
    const int bRow = (t2 >= 0 ? t2 : 0) >> 5;
    const int bCol = ((t2 >= 0 ? t2 : 0) & 31) << 2;
    const float* bPtr = g_w1r + (size_t)bRow * D_ + bn * 128 + bCol;

    const int tx = tid & 31;   // N: tx*4
    const int ty = tid >> 5;   // M: ty*8

    float acc[8][4], comp[8][4], p[8][4];
    #pragma unroll
    for (int i = 0; i < 8; i++)
        #pragma unroll
        for (int j = 0; j < 4; j++) { acc[i][j] = 0.f; comp[i][j] = 0.f; p[i][j] = 0.f; }

    // prologue: stage 0
    if (isA) {
        float4 a = *(const float4*)(aPtr);
        As[0][aCol + 0][aRow] = a.x;
        As[0][aCol + 1][aRow] = a.y;
        As[0][aCol + 2][aRow] = a.z;
        As[0][aCol + 3][aRow] = a.w;
    } else {
        *(float4*)&Bs[0][bRow][bCol] = *(const float4*)(bPtr);
    }
    __syncthreads();

    const int NK = K_DIM / 8;   // 768
    int buf = 0;
    for (int g = 0; g < NK / 4; g++) {
        #pragma unroll
        for (int t4 = 0; t4 < 4; t4++) {
            const int kt = g * 4 + t4;
            const bool more = (kt + 1 < NK);
            float4 nf;
            if (more) {
                nf = isA ? *(const float4*)(aPtr + (kt + 1) * 8)
                         : *(const float4*)(bPtr + (size_t)(kt + 1) * 8 * D_);
            }
            #pragma unroll
            for (int k = 0; k < 8; k++) {
                float4 a0 = *(const float4*)&As[buf][k][ty * 8];
                float4 a1 = *(const float4*)&As[buf][k][ty * 8 + 4];
                float4 bv = *(const float4*)&Bs[buf][k][tx * 4];
                float ar[8] = {a0.x, a0.y, a0.z, a0.w, a1.x, a1.y, a1.z, a1.w};
                float br[4] = {bv.x, bv.y, bv.z, bv.w};
                #pragma unroll
                for (int i = 0; i < 8; i++)
                    #pragma unroll
                    for (int j = 0; j < 4; j++)
                        p[i][j] = fmaf(ar[i], br[j], p[i][j]);
            }
            if (more) {
                if (isA) {
                    As[buf ^ 1][aCol + 0][aRow] = nf.x;
                    As[buf ^ 1][aCol + 1][aRow] = nf.y;
                    As[buf ^ 1][aCol + 2][aRow] = nf.z;
                    As[buf ^ 1][aCol + 3][aRow] = nf.w;
                } else {
                    *(float4*)&Bs[buf ^ 1][bRow][bCol] = nf;
                }
                __syncthreads();
                buf ^= 1;
            }
        }
        // Kahan fold of 32-term partial into (acc, comp)
        #pragma unroll
        for (int i = 0; i < 8; i++)
            #pragma unroll
            for (int j = 0; j < 4; j++) {
                float y = __fsub_rn(p[i][j], comp[i][j]);
                float t = __fadd_rn(acc[i][j], y);
                comp[i][j] = __fsub_rn(__fsub_rn(t, acc[i][j]), y);
                acc[i][j] = t;
                p[i][j] = 0.f;
            }
    }

    // epilogue: (acc+comp) + bias, relu -> g_h
    const int nb = bn * 128 + tx * 4;
    float bias[4];
    #pragma unroll
    for (int j = 0; j < 4; j++) bias[j] = b1[nb + j];
    #pragma unroll
    for (int i = 0; i < 8; i++) {
        int mr = bm * 128 + ty * 8 + i;
        if (mr < M_TOTAL) {
            float4 o;
            o.x = fmaxf(__fadd_rn(acc[i][0], comp[i][0]) + bias[0], 0.f);
            o.y = fmaxf(__fadd_rn(acc[i][1], comp[i][1]) + bias[1], 0.f);
            o.z = fmaxf(__fadd_rn(acc[i][2], comp[i][2]) + bias[2], 0.f);
            o.w = fmaxf(__fadd_rn(acc[i][3], comp[i][3]) + bias[3], 0.f);
            *(float4*)(g_h + (size_t)mr * D_ + nb) = o;
        }
    }
}

// ============================================================
// cas + actionness. fp32 lane partials, warp tree-reduce in fp64,
// per-channel round to fp32 (mimics reference cas), relu, serial fp32 sum.
// ============================================================
__global__ __launch_bounds__(256) void cas_kernel(float* __restrict__ cas,
                                                  float* __restrict__ act) {
    int warp = blockIdx.x * 8 + (threadIdx.x >> 5);
    int lane = threadIdx.x & 31;
    int m0 = warp * 4;
    if (m0 >= M_TOTAL) return;

    float acc[4][20];
    #pragma unroll
    for (int r = 0; r < 4; r++)
        #pragma unroll
        for (int c = 0; c < C_; c++) acc[r][c] = 0.f;

    for (int d = lane; d < D_; d += 32) {
        float w[20];
        const float4* wp = (const float4*)(g_w2t + d * C_);
        #pragma unroll
        for (int q = 0; q < 5; q++) {
            float4 t4 = wp[q];
            w[q * 4 + 0] = t4.x; w[q * 4 + 1] = t4.y;
            w[q * 4 + 2] = t4.z; w[q * 4 + 3] = t4.w;
        }
        #pragma unroll
        for (int r = 0; r < 4; r++) {
            float hv = g_h[(size_t)(m0 + r) * D_ + d];
            #pragma unroll
            for (int c = 0; c < C_; c++) acc[r][c] = fmaf(hv, w[c], acc[r][c]);
        }
    }
    #pragma unroll
    for (int r = 0; r < 4; r++) {
        float s = 0.f;
        #pragma unroll
        for (int c = 0; c < C_; c++) {
            double v = (double)acc[r][c];
            #pragma unroll
            for (int off = 16; off; off >>= 1)
                v += __shfl_down_sync(0xffffffffu, v, off);
            if (lane == 0) {
                float cf = fmaxf((float)v, 0.f);
                cas[(size_t)(m0 + r) * C_ + c] = cf;
                s = __fadd_rn(s, cf);
            }
        }
        if (lane == 0) act[m0 + r] = s;
    }
}

// ============================================================
// bitonic sort: descending value, tie -> smaller index first.
// ============================================================
__device__ __forceinline__ void bitonic_sort_desc(float* val, int* idx, int tid) {
    for (int k = 2; k <= 1024; k <<= 1) {
        for (int j = k >> 1; j > 0; j >>= 1) {
            int p = tid ^ j;
            if (p > tid) {
                float v1 = val[tid], v2 = val[p];
                int i1 = idx[tid], i2 = idx[p];
                bool dirFwd = ((tid & k) == 0);
                bool p_before = (v2 > v1) || (v2 == v1 && i2 < i1);
                if (p_before == dirFwd) {
                    val[tid] = v2; val[p] = v1;
                    idx[tid] = i2; idx[p] = i1;
                }
            }
            __syncthreads();
        }
    }
}

// ============================================================
// per-batch top-k index selection (all four sets)
// ============================================================
__global__ __launch_bounds__(1024) void batch_topk(const float* __restrict__ act) {
    __shared__ float s_act[T_];
    __shared__ float s_bin[T_];
    __shared__ float s_val[1024];
    __shared__ int   s_idx[1024];
    __shared__ float s_med, s_max;

    const int b = blockIdx.x, tid = threadIdx.x;
    const float NEG = -CUDART_INF_F;

    if (tid < T_) s_act[tid] = act[b * T_ + tid];
    __syncthreads();

    // block max of actionness (exact, order-insensitive)
    s_val[tid] = (tid < T_) ? s_act[tid] : NEG;
    __syncthreads();
    for (int off = 512; off; off >>= 1) {
        if (tid < off) s_val[tid] = fmaxf(s_val[tid], s_val[tid + off]);
        __syncthreads();
    }
    if (tid == 0) s_max = s_val[0];
    __syncthreads();

    // sort 1: descending actionness -> easy_act indices, median
    s_val[tid] = (tid < T_) ? s_act[tid] : NEG;
    s_idx[tid] = (tid < T_) ? tid : (1 << 20);
    __syncthreads();
    bitonic_sort_desc(s_val, s_idx, tid);
    if (tid < K_EASY) g_idx[b * K_EASY + tid] = s_idx[tid];
    if (tid == 0) s_med = 0.5f * (s_val[374] + s_val[375]);
    __syncthreads();

    // sort 2: descending (max - a) -> easy_bkg indices (exact ref key incl. fp ties)
    s_val[tid] = (tid < T_) ? __fsub_rn(s_max, s_act[tid]) : NEG;
    s_idx[tid] = (tid < T_) ? tid : (1 << 20);
    __syncthreads();
    bitonic_sort_desc(s_val, s_idx, tid);
    if (tid < K_EASY) g_idx[B_ * K_EASY + b * K_EASY + tid] = s_idx[tid];
    __syncthreads();

    if (tid < T_) s_bin[tid] = (s_act[tid] > s_med) ? 1.0f : 0.0f;
    __syncthreads();

    // inner band = erode3 - erode6
    float sc = NEG;
    if (tid < T_) {
        float e3 = 1.f, e6 = 1.f;
        #pragma unroll
        for (int u = -1; u <= 1; u++) {
            int q = tid + u;
            e3 = fminf(e3, (q >= 0 && q < T_) ? s_bin[q] : 0.f);
        }
        #pragma unroll
        for (int u = -3; u <= 2; u++) {
            int q = tid + u;
            e6 = fminf(e6, (q >= 0 && q < T_) ? s_bin[q] : 0.f);
        }
        sc = s_act[tid] * (e3 - e6);
    }
    s_val[tid] = (tid < T_) ? sc : NEG;
    s_idx[tid] = (tid < T_) ? tid : (1 << 20);
    __syncthreads();
    bitonic_sort_desc(s_val, s_idx, tid);
    if (tid < K_HARD) g_idx[2 * B_ * K_EASY + b * K_HARD + tid] = s_idx[tid];
    __syncthreads();

    // outer band = dilate6 - dilate3
    sc = NEG;
    if (tid < T_) {
        float d3 = 0.f, d6 = 0.f;
        #pragma unroll
        for (int u = -1; u <= 1; u++) {
            int q = tid + u;
            d3 = fmaxf(d3, (q >= 0 && q < T_) ? s_bin[q] : 0.f);
        }
        #pragma unroll
        for (int u = -2; u <= 3; u++) {
            int q = tid + u;
            d6 = fmaxf(d6, (q >= 0 && q < T_) ? s_bin[q] : 0.f);
        }
        sc = s_act[tid] * (d6 - d3);
    }
    s_val[tid] = (tid < T_) ? sc : NEG;
    s_idx[tid] = (tid < T_) ? tid : (1 << 20);
    __syncthreads();
    bitonic_sort_desc(s_val, s_idx, tid);
    if (tid < K_HARD)
        g_idx[2 * B_ * K_EASY + B_ * K_HARD + b * K_HARD + tid] = s_idx[tid];
}

// ============================================================
__global__ __launch_bounds__(1024) void video_topk(const float* __restrict__ cas) {
    __shared__ float s_val[1024];
    __shared__ int   s_idx[1024];
    __shared__ float red[32];
    int bc = blockIdx.x;
    int b = bc / C_, c = bc - b * C_;
    int tid = threadIdx.x;
    s_val[tid] = (tid < T_) ? cas[(size_t)(b * T_ + tid) * C_ + c] : -CUDART_INF_F;
    s_idx[tid] = tid;
    __syncthreads();
    bitonic_sort_desc(s_val, s_idx, tid);
    float v = (tid < K_EASY) ? s_val[tid] : 0.f;
    #pragma unroll
    for (int off = 16; off; off >>= 1) v += __shfl_down_sync(0xffffffffu, v, off);
    if ((tid & 31) == 0) red[tid >> 5] = v;
    __syncthreads();
    if (tid < 32) {
        float t = (tid < 32) ? red[tid] : 0.f;
        #pragma unroll
        for (int off = 16; off; off >>= 1) t += __shfl_down_sync(0xffffffffu, t, off);
        if (tid == 0) g_means[b * C_ + c] = t / (float)K_EASY;
    }
}

__global__ void softmax_k(float* __restrict__ out) {
    int b = blockIdx.x;
    int lane = threadIdx.x;
    float v = (lane < C_) ? g_means[b * C_ + lane] : -CUDART_INF_F;
    float mx = v;
    #pragma unroll
    for (int off = 16; off; off >>= 1) mx = fmaxf(mx, __shfl_xor_sync(0xffffffffu, mx, off));
    float e = (lane < C_) ? expf(v - mx) : 0.f;
    float s = e;
    #pragma unroll
    for (int off = 16; off; off >>= 1) s += __shfl_xor_sync(0xffffffffu, s, off);
    if (lane < C_) out[b * C_ + lane] = e / s;
}

__global__ __launch_bounds__(256) void gather_k(float* __restrict__ out) {
    int r = blockIdx.x;
    int b, t;
    size_t dst;
    if (r < B_ * K_EASY) {
        b = r / K_EASY; t = g_idx[r];
        dst = OFF_EA + (size_t)r * D_;
    } else if (r < 2 * B_ * K_EASY) {
        int rr = r - B_ * K_EASY;
        b = rr / K_EASY; t = g_idx[r];
        dst = OFF_EB + (size_t)rr * D_;
    } else if (r < 2 * B_ * K_EASY + B_ * K_HARD) {
        int rr = r - 2 * B_ * K_EASY;
        b = rr / K_HARD; t = g_idx[r];
        dst = OFF_HA + (size_t)rr * D_;
    } else {
        int rr = r - 2 * B_ * K_EASY - B_ * K_HARD;
        b = rr / K_HARD; t = g_idx[r];
        dst = OFF_HB + (size_t)rr * D_;
    }
    const float4* src = (const float4*)(g_h + ((size_t)(b * T_ + t) << 11));
    float4* d = (float4*)(out + dst);
    for (int i = threadIdx.x; i < D_ / 4; i += blockDim.x) d[i] = src[i];
}

// ============================================================
extern "C" void kernel_launch(void* const* d_in, const int* in_sizes, int n_in,
                              void* d_out, int out_size) {
    const float* x  = (const float*)d_in[0];
    const float* w1 = (const float*)d_in[1];
    const float* b1 = (const float*)d_in[2];
    const float* w2 = (const float*)d_in[3];
    float* out = (float*)d_out;

    pad_x_k<<<(B_ * 752 * (D_ / 4) + 255) / 256, 256>>>(x);
    {
        dim3 g(K_DIM / 32, D_ / 32), blk(32, 32);
        repack_w1_k<<<g, blk>>>(w1);
    }
    repack_w2_k<<<(D_ * C_ + 255) / 256, 256>>>(w2);
    {
        dim3 g(D_ / 128, (M_TOTAL + 127) / 128);
        conv1_gemm<<<g, 512>>>(b1);
    }
    cas_kernel<<<(M_TOTAL / 4 + 7) / 8, 256>>>(out + OFF_CAS, out + OFF_ACT);
    batch_topk<<<B_, 1024>>>(out + OFF_ACT);
    video_topk<<<B_ * C_, 1024>>>(out + OFF_CAS);
    softmax_k<<<B_, 32>>>(out + OFF_VS);
    gather_k<<<2 * B_ * K_EASY + 2 * B_ * K_HARD, 256>>>(out);
}

// round 4
// speedup vs baseline: 1.6855x; 1.6855x over previous
#include <cuda_runtime.h>
#include <math_constants.h>
#include <cstddef>
#include <cstdint>

#define B_  16
#define T_  750
#define D_  2048
#define C_  20
constexpr int M_TOTAL = B_ * T_;     // 12000
constexpr int K_DIM   = 3 * D_;      // 6144
constexpr int K_EASY  = T_ / 5;      // 150
constexpr int K_HARD  = T_ / 20;     // 37

// ---- output offsets (flattened reference tuple, all f32) ----
constexpr size_t OFF_VS  = 0;
constexpr size_t OFF_EA  = OFF_VS + (size_t)B_ * C_;
constexpr size_t OFF_EB  = OFF_EA + (size_t)B_ * K_EASY * D_;
constexpr size_t OFF_HA  = OFF_EB + (size_t)B_ * K_EASY * D_;
constexpr size_t OFF_HB  = OFF_HA + (size_t)B_ * K_HARD * D_;
constexpr size_t OFF_ACT = OFF_HB + (size_t)B_ * K_HARD * D_;
constexpr size_t OFF_CAS = OFF_ACT + (size_t)B_ * T_;

// ---- scratch ----
__device__ float g_xp[(size_t)B_ * 752 * D_];
__device__ float g_w1r[(size_t)K_DIM * D_];
__device__ float g_w2t[D_ * C_];
__device__ float g_h[(size_t)M_TOTAL * D_];
__device__ int   g_idx[2 * (B_ * K_EASY) + 2 * (B_ * K_HARD)];
__device__ float g_means[B_ * C_];

// ============================================================
__global__ void pad_x_k(const float* __restrict__ x) {
    int idx = blockIdx.x * blockDim.x + threadIdx.x;
    const int per_b = 752 * (D_ / 4);
    if (idx >= B_ * per_b) return;
    int b  = idx / per_b;
    int r  = idx - b * per_b;
    int t  = r >> 9;
    int d4 = r & 511;
    float4 v = make_float4(0.f, 0.f, 0.f, 0.f);
    if (t >= 1 && t <= T_) {
        v = ((const float4*)x)[((size_t)(b * T_ + (t - 1)) << 9) + d4];
    }
    ((float4*)g_xp)[idx] = v;
}

__global__ void repack_w1_k(const float* __restrict__ w1) {
    __shared__ float sh[32][33];
    int ic0 = blockIdx.x * 32;
    int d0  = blockIdx.y * 32;
    int tx = threadIdx.x, ty = threadIdx.y;
    sh[ty][tx] = w1[(size_t)(d0 + ty) * K_DIM + ic0 + tx];
    __syncthreads();
    int ic = ic0 + ty;
    int io = ic / 3, ko = ic - io * 3;
    g_w1r[((size_t)(ko * D_ + io)) * D_ + d0 + tx] = sh[tx][ty];
}

__global__ void repack_w2_k(const float* __restrict__ w2) {
    int o = blockIdx.x * blockDim.x + threadIdx.x;
    if (o >= D_ * C_) return;
    int d = o / C_, c = o - d * C_;
    g_w2t[o] = w2[(size_t)c * D_ + d];
}

// ============================================================
// conv1 as GEMM via 3xTF32 mma.sync, compensated accumulation.
// M=12000(+pad), N=2048, K=6144. CTA 128x128, 8 warps (2x4),
// warp tile 64x32. Stages k=16, double-buffered raw-fp32 smem;
// hi/lo split done in registers (hi = mantissa mask, exact).
// ============================================================
constexpr int GSTAGES = K_DIM / 16;   // 384
constexpr int A_RS = 20;              // A row stride (floats)
constexpr int B_RS = 136;             // B row stride (floats)
constexpr int A_TILE_F = 128 * A_RS;  // 2560
constexpr int B_TILE_F = 16 * B_RS;   // 2176

__device__ __forceinline__ void split2(float v, uint32_t& hi, uint32_t& lo) {
    uint32_t u = __float_as_uint(v);
    hi = u & 0xffffe000u;
    lo = __float_as_uint(__fsub_rn(v, __uint_as_float(hi)));
}

#define MMA_TF32(c, a0, a1, a2, a3, b0, b1) \
    asm volatile("mma.sync.aligned.m16n8k8.row.col.f32.tf32.tf32.f32 " \
        "{%0,%1,%2,%3}, {%4,%5,%6,%7}, {%8,%9}, {%0,%1,%2,%3};" \
        : "+f"((c)[0]), "+f"((c)[1]), "+f"((c)[2]), "+f"((c)[3]) \
        : "r"(a0), "r"(a1), "r"(a2), "r"(a3), "r"(b0), "r"(b1))

__global__ __launch_bounds__(256, 1) void conv1_tf32(const float* __restrict__ b1) {
    __shared__ float smA[2 * A_TILE_F];   // [buf][128][20]
    __shared__ float smB[2 * B_TILE_F];   // [buf][16][136]

    const int tid  = threadIdx.x;
    const int lane = tid & 31;
    const int wid  = tid >> 5;
    const int wm   = wid & 1;
    const int wn   = wid >> 1;
    const int bn   = blockIdx.x;
    const int bm   = blockIdx.y;
    const int tig  = lane & 3;
    const int gid  = lane >> 2;

    // gmem A: thread owns 8 floats of one m row per stage
    const int arow  = tid >> 1;
    const int akoff = (tid & 1) << 3;
    int mg = bm * 128 + arow;
    int mc = (mg < M_TOTAL) ? mg : 0;
    int bb = mc / T_, tt = mc - bb * T_;
    const float* aSrc = g_xp + (((size_t)(bb * 752 + tt)) << 11) + akoff;

    // gmem B: thread owns 8 floats of one k row per stage
    const int krow = tid >> 4;
    const int n8   = (tid & 15) << 3;
    const float* bSrc = g_w1r + (size_t)krow * D_ + bn * 128 + n8;

    float acc[4][4][4], cfr[4][4][4];
    #pragma unroll
    for (int i = 0; i < 4; i++)
        #pragma unroll
        for (int j = 0; j < 4; j++)
            #pragma unroll
            for (int q = 0; q < 4; q++) { acc[i][j][q] = 0.f; cfr[i][j][q] = 0.f; }

    float4 aR0, aR1, bR0, bR1;

    // prologue: stage 0 -> buf 0
    {
        const float4* ap = (const float4*)aSrc;
        aR0 = ap[0]; aR1 = ap[1];
        const float4* bp = (const float4*)bSrc;
        bR0 = bp[0]; bR1 = bp[1];
        *(float4*)&smA[arow * A_RS + akoff]     = aR0;
        *(float4*)&smA[arow * A_RS + akoff + 4] = aR1;
        *(float4*)&smB[krow * B_RS + n8]     = bR0;
        *(float4*)&smB[krow * B_RS + n8 + 4] = bR1;
    }
    __syncthreads();

    #pragma unroll 1
    for (int s = 0; s < GSTAGES; s++) {
        const int buf = s & 1;
        const float* As = smA + buf * A_TILE_F;
        const float* Bs = smB + buf * B_TILE_F;
        const bool more = (s + 1 < GSTAGES);
        if (more) {
            const float4* ap = (const float4*)(aSrc + (s + 1) * 16);
            aR0 = ap[0]; aR1 = ap[1];
            const float4* bp = (const float4*)(bSrc + (size_t)(s + 1) * 16 * D_);
            bR0 = bp[0]; bR1 = bp[1];
        }

        #pragma unroll
        for (int u = 0; u < 2; u++) {
            // B fragments: raw -> split
            uint32_t bh[4][2], bl[4][2];
            #pragma unroll
            for (int nt = 0; nt < 4; nt++) {
                int nn = wn * 32 + nt * 8 + gid;
                float r0 = Bs[(u * 8 + tig)     * B_RS + nn];
                float r1 = Bs[(u * 8 + 4 + tig) * B_RS + nn];
                split2(r0, bh[nt][0], bl[nt][0]);
                split2(r1, bh[nt][1], bl[nt][1]);
            }
            // A fragments: raw -> split
            uint32_t ah[4][4], al[4][4];
            #pragma unroll
            for (int mt = 0; mt < 4; mt++) {
                int rb = wm * 64 + mt * 16;
                float r0 = As[(rb + gid)     * A_RS + u * 8 + tig];
                float r1 = As[(rb + gid + 8) * A_RS + u * 8 + tig];
                float r2 = As[(rb + gid)     * A_RS + u * 8 + tig + 4];
                float r3 = As[(rb + gid + 8) * A_RS + u * 8 + tig + 4];
                split2(r0, ah[mt][0], al[mt][0]);
                split2(r1, ah[mt][1], al[mt][1]);
                split2(r2, ah[mt][2], al[mt][2]);
                split2(r3, ah[mt][3], al[mt][3]);
            }
            #pragma unroll
            for (int mt = 0; mt < 4; mt++)
                #pragma unroll
                for (int nt = 0; nt < 4; nt++) {
                    MMA_TF32(cfr[mt][nt], ah[mt][0], ah[mt][1], ah[mt][2], ah[mt][3],
                             bh[nt][0], bh[nt][1]);
                    MMA_TF32(cfr[mt][nt], al[mt][0], al[mt][1], al[mt][2], al[mt][3],
                             bh[nt][0], bh[nt][1]);
                    MMA_TF32(cfr[mt][nt], ah[mt][0], ah[mt][1], ah[mt][2], ah[mt][3],
                             bl[nt][0], bl[nt][1]);
                }
        }

        if (more) {
            float* Ad = smA + (buf ^ 1) * A_TILE_F;
            float* Bd = smB + (buf ^ 1) * B_TILE_F;
            *(float4*)&Ad[arow * A_RS + akoff]     = aR0;
            *(float4*)&Ad[arow * A_RS + akoff + 4] = aR1;
            *(float4*)&Bd[krow * B_RS + n8]     = bR0;
            *(float4*)&Bd[krow * B_RS + n8 + 4] = bR1;
            __syncthreads();
        }

        // fold every 2 stages (g = 32 k-terms): 2Sum, comp rides in cfr
        if (s & 1) {
            #pragma unroll
            for (int mt = 0; mt < 4; mt++)
                #pragma unroll
                for (int nt = 0; nt < 4; nt++)
                    #pragma unroll
                    for (int q = 0; q < 4; q++) {
                        float a = acc[mt][nt][q], c = cfr[mt][nt][q];
                        float sP = __fadd_rn(a, c);
                        float bb2 = __fsub_rn(sP, a);
                        float err = __fadd_rn(__fsub_rn(a, __fsub_rn(sP, bb2)),
                                              __fsub_rn(c, bb2));
                        acc[mt][nt][q] = sP;
                        cfr[mt][nt][q] = err;
                    }
        }
    }

    // epilogue: (acc + cfr) + bias, relu -> g_h
    #pragma unroll
    for (int mt = 0; mt < 4; mt++) {
        #pragma unroll
        for (int r2 = 0; r2 < 2; r2++) {
            int m = bm * 128 + wm * 64 + mt * 16 + gid + r2 * 8;
            if (m < M_TOTAL) {
                #pragma unroll
                for (int nt = 0; nt < 4; nt++) {
                    int n = bn * 128 + wn * 32 + nt * 8 + tig * 2;
                    float v0 = fmaxf(__fadd_rn(__fadd_rn(acc[mt][nt][r2*2+0], cfr[mt][nt][r2*2+0]), b1[n]), 0.f);
                    float v1 = fmaxf(__fadd_rn(__fadd_rn(acc[mt][nt][r2*2+1], cfr[mt][nt][r2*2+1]), b1[n+1]), 0.f);
                    *(float2*)(g_h + (size_t)m * D_ + n) = make_float2(v0, v1);
                }
            }
        }
    }
}

// ============================================================
// cas + actionness (unchanged from passing round 2)
// ============================================================
__global__ __launch_bounds__(256) void cas_kernel(float* __restrict__ cas,
                                                  float* __restrict__ act) {
    int warp = blockIdx.x * 8 + (threadIdx.x >> 5);
    int lane = threadIdx.x & 31;
    int m0 = warp * 4;
    if (m0 >= M_TOTAL) return;

    float acc[4][20];
    #pragma unroll
    for (int r = 0; r < 4; r++)
        #pragma unroll
        for (int c = 0; c < C_; c++) acc[r][c] = 0.f;

    for (int d = lane; d < D_; d += 32) {
        float w[20];
        const float4* wp = (const float4*)(g_w2t + d * C_);
        #pragma unroll
        for (int q = 0; q < 5; q++) {
            float4 t4 = wp[q];
            w[q * 4 + 0] = t4.x; w[q * 4 + 1] = t4.y;
            w[q * 4 + 2] = t4.z; w[q * 4 + 3] = t4.w;
        }
        #pragma unroll
        for (int r = 0; r < 4; r++) {
            float hv = g_h[(size_t)(m0 + r) * D_ + d];
            #pragma unroll
            for (int c = 0; c < C_; c++) acc[r][c] = fmaf(hv, w[c], acc[r][c]);
        }
    }
    #pragma unroll
    for (int r = 0; r < 4; r++) {
        float s = 0.f;
        #pragma unroll
        for (int c = 0; c < C_; c++) {
            double v = (double)acc[r][c];
            #pragma unroll
            for (int off = 16; off; off >>= 1)
                v += __shfl_down_sync(0xffffffffu, v, off);
            if (lane == 0) {
                float cf = fmaxf((float)v, 0.f);
                cas[(size_t)(m0 + r) * C_ + c] = cf;
                s = __fadd_rn(s, cf);
            }
        }
        if (lane == 0) act[m0 + r] = s;
    }
}

// ============================================================
__device__ __forceinline__ void bitonic_sort_desc(float* val, int* idx, int tid) {
    for (int k = 2; k <= 1024; k <<= 1) {
        for (int j = k >> 1; j > 0; j >>= 1) {
            int p = tid ^ j;
            if (p > tid) {
                float v1 = val[tid], v2 = val[p];
                int i1 = idx[tid], i2 = idx[p];
                bool dirFwd = ((tid & k) == 0);
                bool p_before = (v2 > v1) || (v2 == v1 && i2 < i1);
                if (p_before == dirFwd) {
                    val[tid] = v2; val[p] = v1;
                    idx[tid] = i2; idx[p] = i1;
                }
            }
            __syncthreads();
        }
    }
}

__global__ __launch_bounds__(1024) void batch_topk(const float* __restrict__ act) {
    __shared__ float s_act[T_];
    __shared__ float s_bin[T_];
    __shared__ float s_val[1024];
    __shared__ int   s_idx[1024];
    __shared__ float s_med, s_max;

    const int b = blockIdx.x, tid = threadIdx.x;
    const float NEG = -CUDART_INF_F;

    if (tid < T_) s_act[tid] = act[b * T_ + tid];
    __syncthreads();

    s_val[tid] = (tid < T_) ? s_act[tid] : NEG;
    __syncthreads();
    for (int off = 512; off; off >>= 1) {
        if (tid < off) s_val[tid] = fmaxf(s_val[tid], s_val[tid + off]);
        __syncthreads();
    }
    if (tid == 0) s_max = s_val[0];
    __syncthreads();

    s_val[tid] = (tid < T_) ? s_act[tid] : NEG;
    s_idx[tid] = (tid < T_) ? tid : (1 << 20);
    __syncthreads();
    bitonic_sort_desc(s_val, s_idx, tid);
    if (tid < K_EASY) g_idx[b * K_EASY + tid] = s_idx[tid];
    if (tid == 0) s_med = 0.5f * (s_val[374] + s_val[375]);
    __syncthreads();

    s_val[tid] = (tid < T_) ? __fsub_rn(s_max, s_act[tid]) : NEG;
    s_idx[tid] = (tid < T_) ? tid : (1 << 20);
    __syncthreads();
    bitonic_sort_desc(s_val, s_idx, tid);
    if (tid < K_EASY) g_idx[B_ * K_EASY + b * K_EASY + tid] = s_idx[tid];
    __syncthreads();

    if (tid < T_) s_bin[tid] = (s_act[tid] > s_med) ? 1.0f : 0.0f;
    __syncthreads();

    float sc = NEG;
    if (tid < T_) {
        float e3 = 1.f, e6 = 1.f;
        #pragma unroll
        for (int u = -1; u <= 1; u++) {
            int q = tid + u;
            e3 = fminf(e3, (q >= 0 && q < T_) ? s_bin[q] : 0.f);
        }
        #pragma unroll
        for (int u = -3; u <= 2; u++) {
            int q = tid + u;
            e6 = fminf(e6, (q >= 0 && q < T_) ? s_bin[q] : 0.f);
        }
        sc = s_act[tid] * (e3 - e6);
    }
    s_val[tid] = (tid < T_) ? sc : NEG;
    s_idx[tid] = (tid < T_) ? tid : (1 << 20);
    __syncthreads();
    bitonic_sort_desc(s_val, s_idx, tid);
    if (tid < K_HARD) g_idx[2 * B_ * K_EASY + b * K_HARD + tid] = s_idx[tid];
    __syncthreads();

    sc = NEG;
    if (tid < T_) {
        float d3 = 0.f, d6 = 0.f;
        #pragma unroll
        for (int u = -1; u <= 1; u++) {
            int q = tid + u;
            d3 = fmaxf(d3, (q >= 0 && q < T_) ? s_bin[q] : 0.f);
        }
        #pragma unroll
        for (int u = -2; u <= 3; u++) {
            int q = tid + u;
            d6 = fmaxf(d6, (q >= 0 && q < T_) ? s_bin[q] : 0.f);
        }
        sc = s_act[tid] * (d6 - d3);
    }
    s_val[tid] = (tid < T_) ? sc : NEG;
    s_idx[tid] = (tid < T_) ? tid : (1 << 20);
    __syncthreads();
    bitonic_sort_desc(s_val, s_idx, tid);
    if (tid < K_HARD)
        g_idx[2 * B_ * K_EASY + B_ * K_HARD + b * K_HARD + tid] = s_idx[tid];
}

__global__ __launch_bounds__(1024) void video_topk(const float* __restrict__ cas) {
    __shared__ float s_val[1024];
    __shared__ int   s_idx[1024];
    __shared__ float red[32];
    int bc = blockIdx.x;
    int b = bc / C_, c = bc - b * C_;
    int tid = threadIdx.x;
    s_val[tid] = (tid < T_) ? cas[(size_t)(b * T_ + tid) * C_ + c] : -CUDART_INF_F;
    s_idx[tid] = tid;
    __syncthreads();
    bitonic_sort_desc(s_val, s_idx, tid);
    float v = (tid < K_EASY) ? s_val[tid] : 0.f;
    #pragma unroll
    for (int off = 16; off; off >>= 1) v += __shfl_down_sync(0xffffffffu, v, off);
    if ((tid & 31) == 0) red[tid >> 5] = v;
    __syncthreads();
    if (tid < 32) {
        float t = red[tid];
        #pragma unroll
        for (int off = 16; off; off >>= 1) t += __shfl_down_sync(0xffffffffu, t, off);
        if (tid == 0) g_means[b * C_ + c] = t / (float)K_EASY;
    }
}

__global__ void softmax_k(float* __restrict__ out) {
    int b = blockIdx.x;
    int lane = threadIdx.x;
    float v = (lane < C_) ? g_means[b * C_ + lane] : -CUDART_INF_F;
    float mx = v;
    #pragma unroll
    for (int off = 16; off; off >>= 1) mx = fmaxf(mx, __shfl_xor_sync(0xffffffffu, mx, off));
    float e = (lane < C_) ? expf(v - mx) : 0.f;
    float s = e;
    #pragma unroll
    for (int off = 16; off; off >>= 1) s += __shfl_xor_sync(0xffffffffu, s, off);
    if (lane < C_) out[b * C_ + lane] = e / s;
}

__global__ __launch_bounds__(256) void gather_k(float* __restrict__ out) {
    int r = blockIdx.x;
    int b, t;
    size_t dst;
    if (r < B_ * K_EASY) {
        b = r / K_EASY; t = g_idx[r];
        dst = OFF_EA + (size_t)r * D_;
    } else if (r < 2 * B_ * K_EASY) {
        int rr = r - B_ * K_EASY;
        b = rr / K_EASY; t = g_idx[r];
        dst = OFF_EB + (size_t)rr * D_;
    } else if (r < 2 * B_ * K_EASY + B_ * K_HARD) {
        int rr = r - 2 * B_ * K_EASY;
        b = rr / K_HARD; t = g_idx[r];
        dst = OFF_HA + (size_t)rr * D_;
    } else {
        int rr = r - 2 * B_ * K_EASY - B_ * K_HARD;
        b = rr / K_HARD; t = g_idx[r];
        dst = OFF_HB + (size_t)rr * D_;
    }
    const float4* src = (const float4*)(g_h + ((size_t)(b * T_ + t) << 11));
    float4* d = (float4*)(out + dst);
    for (int i = threadIdx.x; i < D_ / 4; i += blockDim.x) d[i] = src[i];
}

// ============================================================
extern "C" void kernel_launch(void* const* d_in, const int* in_sizes, int n_in,
                              void* d_out, int out_size) {
    const float* x  = (const float*)d_in[0];
    const float* w1 = (const float*)d_in[1];
    const float* b1 = (const float*)d_in[2];
    const float* w2 = (const float*)d_in[3];
    float* out = (float*)d_out;

    pad_x_k<<<(B_ * 752 * (D_ / 4) + 255) / 256, 256>>>(x);
    {
        dim3 g(K_DIM / 32, D_ / 32), blk(32, 32);
        repack_w1_k<<<g, blk>>>(w1);
    }
    repack_w2_k<<<(D_ * C_ + 255) / 256, 256>>>(w2);
    {
        dim3 g(D_ / 128, (M_TOTAL + 127) / 128);   // (16, 94)
        conv1_tf32<<<g, 256>>>(b1);
    }
    cas_kernel<<<(M_TOTAL / 4 + 7) / 8, 256>>>(out + OFF_CAS, out + OFF_ACT);
    batch_topk<<<B_, 1024>>>(out + OFF_ACT);
    video_topk<<<B_ * C_, 1024>>>(out + OFF_CAS);
    softmax_k<<<B_, 32>>>(out + OFF_VS);
    gather_k<<<2 * B_ * K_EASY + 2 * B_ * K_HARD, 256>>>(out);
}